// round 1
// baseline (speedup 1.0000x reference)
#include <cuda_runtime.h>
#include <cstdint>

// Problem constants
constexpr int D_   = 64;      // item dim
constexpr int L_   = 16;      // code length
constexpr int NB_  = 65536;   // buckets

// Tiling
constexpr int BLOCK_ = 64;            // threads per block
constexpr int M_     = 2;             // items per thread
constexpr int TILE_  = BLOCK_ * M_;   // 128 items per block
constexpr int ROWF_  = 68;            // padded row length in floats (17 x 16B -> conflict-free)

// ---------------- f32x2 helpers (sm_103a packed fp32) ----------------
__device__ __forceinline__ uint64_t dup_f32(float x) {
    uint64_t r;
    asm("mov.b64 %0, {%1, %1};" : "=l"(r) : "f"(x));
    return r;
}
__device__ __forceinline__ void fma2(uint64_t& acc, uint64_t a, uint64_t b) {
    asm("fma.rn.f32x2 %0, %1, %2, %0;" : "+l"(acc) : "l"(a), "l"(b));
}
__device__ __forceinline__ void unpack2(uint64_t v, float& lo, float& hi) {
    asm("mov.b64 {%0, %1}, %2;" : "=f"(lo), "=f"(hi) : "l"(v));
}
__device__ __forceinline__ void cp_async16(void* smem_dst, const void* gsrc) {
    unsigned s = (unsigned)__cvta_generic_to_shared(smem_dst);
    asm volatile("cp.async.cg.shared.global [%0], [%1], 16;" :: "r"(s), "l"(gsrc));
}

// ---------------- counts init (d_out is poisoned; seed from input counts) ----
__global__ void init_counts_kernel(float* __restrict__ outCounts,
                                   const float* __restrict__ counts, int nb) {
    int i = blockIdx.x * blockDim.x + threadIdx.x;
    if (i < nb) outCounts[i] = counts[i];
}

// ---------------- main kernel ----------------
__global__ __launch_bounds__(BLOCK_)
void hash_counter_kernel(const float* __restrict__ items,
                         const float* __restrict__ W,
                         float* __restrict__ outBuckets,
                         float* __restrict__ outCounts,
                         int n, int asInt) {
    __shared__ float sIt[TILE_ * ROWF_];   // padded item tile (34,816 B)
    __shared__ float sW[D_ * L_];          // W_hash row-major [64][16] (4 KB)

    const int tid = threadIdx.x;
    const long base = (long)blockIdx.x * TILE_;

    // Stage W: 1024 floats = 256 float4, 4 per thread (uniform broadcast later)
    #pragma unroll
    for (int i = 0; i < (D_ * L_ / 4) / BLOCK_; ++i) {
        int idx = tid + i * BLOCK_;
        cp_async16(&sW[idx * 4], W + idx * 4);
    }
    // Stage items: TILE_ rows x 64 floats, contiguous in global, padded in smem
    const float* gbase = items + base * D_;
    #pragma unroll
    for (int i = 0; i < TILE_ * (D_ / 4) / BLOCK_; ++i) {   // 32 iters
        int idx = tid + i * BLOCK_;                          // float4 index in tile
        int row = idx >> 4;
        int col = idx & 15;
        if (base + row < n)
            cp_async16(&sIt[row * ROWF_ + col * 4], gbase + (size_t)idx * 4);
    }
    asm volatile("cp.async.commit_group;\ncp.async.wait_group 0;" ::: "memory");
    __syncthreads();

    // 8 packed accumulators per item: acc[m][j] = (dot_{2j}, dot_{2j+1})
    uint64_t acc[M_][8];
    #pragma unroll
    for (int m = 0; m < M_; ++m)
        #pragma unroll
        for (int j = 0; j < 8; ++j) acc[m][j] = 0ull;   // (+0.0f, +0.0f)

    #pragma unroll
    for (int c = 0; c < 16; ++c) {          // k-chunk of 4
        float4 v[M_];
        #pragma unroll
        for (int m = 0; m < M_; ++m)
            v[m] = *reinterpret_cast<const float4*>(
                       &sIt[(tid + m * BLOCK_) * ROWF_ + c * 4]);

        #pragma unroll
        for (int kk = 0; kk < 4; ++kk) {
            const int k = c * 4 + kk;
            // W row k: 16 floats = 8 f32x2 pairs, loaded as 4x LDS.128 (uniform)
            const ulonglong2* wr = reinterpret_cast<const ulonglong2*>(&sW[k * L_]);
            ulonglong2 wA = wr[0], wB = wr[1], wC = wr[2], wD = wr[3];
            uint64_t wq[8] = {wA.x, wA.y, wB.x, wB.y, wC.x, wC.y, wD.x, wD.y};

            #pragma unroll
            for (int m = 0; m < M_; ++m) {
                float vk = (kk == 0) ? v[m].x : (kk == 1) ? v[m].y
                         : (kk == 2) ? v[m].z : v[m].w;
                uint64_t dv = dup_f32(vk);
                #pragma unroll
                for (int j = 0; j < 8; ++j) fma2(acc[m][j], dv, wq[j]);
            }
        }
    }

    // Sign bits -> bucket; write + histogram
    #pragma unroll
    for (int m = 0; m < M_; ++m) {
        long gi = base + tid + m * BLOCK_;
        if (gi < n) {
            unsigned b = 0;
            #pragma unroll
            for (int j = 0; j < 8; ++j) {
                float lo, hi;
                unpack2(acc[m][j], lo, hi);
                if (lo >= 0.0f) b |= 1u << (15 - 2 * j);
                if (hi >= 0.0f) b |= 1u << (14 - 2 * j);
            }
            if (outBuckets) {
                if (asInt) reinterpret_cast<int*>(outBuckets)[gi] = (int)b;
                else       outBuckets[gi] = (float)b;
            }
            if (outCounts) atomicAdd(&outCounts[b], 1.0f);
        }
    }
}

// ---------------- launch ----------------
extern "C" void kernel_launch(void* const* d_in, const int* in_sizes, int n_in,
                              void* d_out, int out_size) {
    const float* items  = (const float*)d_in[0];
    const float* W      = (const float*)d_in[1];
    const float* counts = (const float*)d_in[2];
    const int n = in_sizes[0] / D_;

    float* out = (float*)d_out;
    float* outBuckets = nullptr;
    float* outCounts  = nullptr;
    int asInt = 0;

    if (out_size >= n + NB_) {           // expected: concatenated (buckets, counts) as f32
        outBuckets = out;
        outCounts  = out + n;
    } else if (out_size == NB_) {        // counts only
        outCounts = out;
    } else {                             // buckets only -> keep reference dtype (int32)
        outBuckets = out;
        asInt = 1;
    }

    if (outCounts)
        init_counts_kernel<<<(NB_ + 255) / 256, 256>>>(outCounts, counts, NB_);

    const int grid = (n + TILE_ - 1) / TILE_;
    hash_counter_kernel<<<grid, BLOCK_>>>(items, W, outBuckets, outCounts, n, asInt);
}

// round 3
// speedup vs baseline: 1.2517x; 1.2517x over previous
#include <cuda_runtime.h>
#include <cstdint>

// Problem constants
constexpr int D_   = 64;      // item dim
constexpr int L_   = 16;      // code length
constexpr int NB_  = 65536;   // buckets

// Tiling
constexpr int BLOCK_ = 64;            // threads per block
constexpr int M_     = 4;             // items per thread
constexpr int TILE_  = BLOCK_ * M_;   // 256 items per block

// ---------------- f32x2 helpers (sm_103a packed fp32) ----------------
__device__ __forceinline__ uint64_t dup_f32(float x) {
    uint64_t r;
    asm("mov.b64 %0, {%1, %1};" : "=l"(r) : "f"(x));
    return r;
}
__device__ __forceinline__ void fma2(uint64_t& acc, uint64_t a, uint64_t b) {
    asm("fma.rn.f32x2 %0, %1, %2, %0;" : "+l"(acc) : "l"(a), "l"(b));
}
__device__ __forceinline__ void unpack2(uint64_t v, float& lo, float& hi) {
    asm("mov.b64 {%0, %1}, %2;" : "=f"(lo), "=f"(hi) : "l"(v));
}
__device__ __forceinline__ void cp_async16(void* smem_dst, const void* gsrc) {
    unsigned s = (unsigned)__cvta_generic_to_shared(smem_dst);
    asm volatile("cp.async.cg.shared.global [%0], [%1], 16;" :: "r"(s), "l"(gsrc));
}

// ---------------- counts init (d_out is poisoned; seed from input counts) ----
__global__ void init_counts_kernel(float* __restrict__ outCounts,
                                   const float* __restrict__ counts, int nb) {
    int i = blockIdx.x * blockDim.x + threadIdx.x;
    if (i < nb) outCounts[i] = counts[i];
}

// ---------------- main kernel ----------------
__global__ __launch_bounds__(BLOCK_)
void hash_counter_kernel(const float* __restrict__ items,
                         const float* __restrict__ W,
                         float* __restrict__ outBuckets,
                         float* __restrict__ outCounts,
                         int n, int asInt) {
    // Item tile: 256 rows x 64 floats (256B/row), XOR-swizzled 16B chunks.
    // chunk c of row r lives at float offset r*64 + ((c ^ (r & 15)) * 4)
    // -> conflict-free for both coalesced cp.async stores and strided reads.
    __shared__ float sIt[TILE_ * D_];      // 65,536 B
    __shared__ float sW[D_ * L_];          // W_hash row-major [64][16] (4 KB)

    const int tid = threadIdx.x;
    const long base = (long)blockIdx.x * TILE_;

    // Stage W: 1024 floats = 256 float4, 4 per thread
    #pragma unroll
    for (int i = 0; i < (D_ * L_ / 4) / BLOCK_; ++i) {
        int idx = tid + i * BLOCK_;
        cp_async16(&sW[idx * 4], W + idx * 4);
    }
    // Stage items: TILE_ rows x 64 floats, contiguous in global, swizzled in smem
    const float* gbase = items + base * D_;
    #pragma unroll
    for (int i = 0; i < TILE_ * (D_ / 4) / BLOCK_; ++i) {   // 64 iters
        int idx = tid + i * BLOCK_;                          // float4 index in tile
        int row = idx >> 4;
        int col = idx & 15;
        int scol = col ^ (row & 15);
        if (base + row < n)
            cp_async16(&sIt[row * D_ + scol * 4], gbase + (size_t)idx * 4);
    }
    asm volatile("cp.async.commit_group;\ncp.async.wait_group 0;" ::: "memory");
    __syncthreads();

    // 8 packed accumulators per item: acc[m][j] = (dot_{2j}, dot_{2j+1})
    uint64_t acc[M_][8];
    #pragma unroll
    for (int m = 0; m < M_; ++m)
        #pragma unroll
        for (int j = 0; j < 8; ++j) acc[m][j] = 0ull;   // (+0.0f, +0.0f)

    #pragma unroll 4
    for (int c = 0; c < 16; ++c) {          // k-chunk of 4
        float4 v[M_];
        #pragma unroll
        for (int m = 0; m < M_; ++m) {
            int r = tid + m * BLOCK_;
            int scol = c ^ (r & 15);
            v[m] = *reinterpret_cast<const float4*>(&sIt[r * D_ + scol * 4]);
        }

        #pragma unroll
        for (int kk = 0; kk < 4; ++kk) {
            const int k = c * 4 + kk;
            // W row k: 16 floats = 8 f32x2 pairs, loaded as 4x LDS.128 (uniform)
            const ulonglong2* wr = reinterpret_cast<const ulonglong2*>(&sW[k * L_]);
            ulonglong2 wA = wr[0], wB = wr[1], wC = wr[2], wD = wr[3];
            uint64_t wq[8] = {wA.x, wA.y, wB.x, wB.y, wC.x, wC.y, wD.x, wD.y};

            #pragma unroll
            for (int m = 0; m < M_; ++m) {
                float vk = (kk == 0) ? v[m].x : (kk == 1) ? v[m].y
                         : (kk == 2) ? v[m].z : v[m].w;
                uint64_t dv = dup_f32(vk);
                #pragma unroll
                for (int j = 0; j < 8; ++j) fma2(acc[m][j], dv, wq[j]);
            }
        }
    }

    // Sign bits -> bucket; write + histogram
    #pragma unroll
    for (int m = 0; m < M_; ++m) {
        long gi = base + tid + m * BLOCK_;
        if (gi < n) {
            unsigned b = 0;
            #pragma unroll
            for (int j = 0; j < 8; ++j) {
                float lo, hi;
                unpack2(acc[m][j], lo, hi);
                if (lo >= 0.0f) b |= 1u << (15 - 2 * j);
                if (hi >= 0.0f) b |= 1u << (14 - 2 * j);
            }
            if (outBuckets) {
                if (asInt) reinterpret_cast<int*>(outBuckets)[gi] = (int)b;
                else       outBuckets[gi] = (float)b;
            }
            if (outCounts) atomicAdd(&outCounts[b], 1.0f);
        }
    }
}

// ---------------- launch ----------------
extern "C" void kernel_launch(void* const* d_in, const int* in_sizes, int n_in,
                              void* d_out, int out_size) {
    const float* items  = (const float*)d_in[0];
    const float* W      = (const float*)d_in[1];
    const float* counts = (const float*)d_in[2];
    const int n = in_sizes[0] / D_;

    float* out = (float*)d_out;
    float* outBuckets = nullptr;
    float* outCounts  = nullptr;
    int asInt = 0;

    if (out_size >= n + NB_) {           // expected: concatenated (buckets, counts) as f32
        outBuckets = out;
        outCounts  = out + n;
    } else if (out_size == NB_) {        // counts only
        outCounts = out;
    } else {                             // buckets only -> keep reference dtype (int32)
        outBuckets = out;
        asInt = 1;
    }

    if (outCounts)
        init_counts_kernel<<<(NB_ + 255) / 256, 256>>>(outCounts, counts, NB_);

    const int grid = (n + TILE_ - 1) / TILE_;
    hash_counter_kernel<<<grid, BLOCK_>>>(items, W, outBuckets, outCounts, n, asInt);
}